// round 10
// baseline (speedup 1.0000x reference)
#include <cuda_runtime.h>
#include <cstdint>

#define BB 16
#define TT 512
#define DD 384
#define OUT_LEN 3584            // T * (MAX_DUR - 1)
#define MAXD 8
#define V4 (DD / 4)             // 96 float4 per row
#define SRC_ROWS 8              // source rows per src block
#define SRC_BLOCKS (TT / SRC_ROWS)      // 64
#define ZROWS 64                // output rows per pad block
#define ZBLOCKS (OUT_LEN / ZROWS)       // 56
#define NT 256

// Source-centric fused kernel:
//  bx <  SRC_BLOCKS: scan + read 8 src rows once (regs) + replicate-store d times
//  bx >= SRC_BLOCKS: reduce total + zero-fill pad overlap
__global__ void __launch_bounds__(NT, 6)
lr_kernel(const float* __restrict__ xs, const int* __restrict__ ds,
          const int* __restrict__ ilens, float* __restrict__ out) {
    __shared__ int csum[TT];
    __shared__ int wtot[8];

    const int tid = threadIdx.x;
    const int lane = tid & 31;
    const int w = tid >> 5;               // 8 warps
    const int b = blockIdx.y;
    const int bx = blockIdx.x;

    // ---- masked duration load: 2 consecutive per thread ----
    const int ilen = __ldg(ilens + b);
    int2 dv = ((const int2*)(ds + b * TT))[tid];
    const int g0 = tid * 2;
    int d0 = (g0 + 0 < ilen) ? dv.x : 0;
    int d1 = (g0 + 1 < ilen) ? dv.y : 0;
    int p1 = d0 + d1;

    float4* __restrict__ ob = (float4*)out + (size_t)b * OUT_LEN * V4;

    if (bx < SRC_BLOCKS) {
        // ================= source-centric block =================
        // Block inclusive scan -> csum[0..511].
        int x = p1;
        #pragma unroll
        for (int off = 1; off < 32; off <<= 1) {
            int y = __shfl_up_sync(0xFFFFFFFFu, x, off);
            if (lane >= off) x += y;
        }
        if (lane == 31) wtot[w] = x;
        __syncthreads();
        int woff = 0;
        #pragma unroll
        for (int i = 0; i < 8; ++i) woff += (i < w) ? wtot[i] : 0;
        const int excl = woff + x - p1;
        csum[g0 + 0] = excl + d0;
        csum[g0 + 1] = excl + p1;
        __syncthreads();

        const int r0 = bx * SRC_ROWS;
        const float4* __restrict__ xb = (const float4*)xs + (size_t)b * TT * V4;

        // 24 warp-tasks: (row_local 0..7) x (third 0..2); warp w takes w, w+8, w+16.
        int rr[3], pp[3], dd[3], cc[3];
        float4 vv[3];
        #pragma unroll
        for (int i = 0; i < 3; ++i) {
            const int tk = w + 8 * i;
            const int row_local = tk / 3;
            const int third = tk - row_local * 3;
            const int r = r0 + row_local;
            const int c = third * 32 + lane;
            const int cend = csum[r];
            const int prev = (r == 0) ? 0 : csum[r - 1];
            rr[i] = r; cc[i] = c; pp[i] = prev; dd[i] = cend - prev;
            vv[i] = xb[r * V4 + c];              // coalesced 512B, read ONCE
        }
        #pragma unroll
        for (int i = 0; i < 3; ++i) {
            const int d = dd[i];
            float4* dst = ob + (size_t)pp[i] * V4 + cc[i];
            #pragma unroll
            for (int j = 0; j < MAXD - 1; ++j) {  // d in [0,7]
                if (j < d) dst[(size_t)j * V4] = vv[i];   // coalesced 512B
            }
        }
    } else {
        // ================= pad zero-fill block =================
        int x = p1;
        #pragma unroll
        for (int off = 16; off > 0; off >>= 1)
            x += __shfl_down_sync(0xFFFFFFFFu, x, off);
        if (lane == 0) wtot[w] = x;
        __syncthreads();
        int total = 0;
        #pragma unroll
        for (int i = 0; i < 8; ++i) total += wtot[i];

        const int r0z = (bx - SRC_BLOCKS) * ZROWS;
        const int start = max(total, r0z);
        const int end = r0z + ZROWS;
        if (start < end) {
            const int nf4 = (end - start) * V4;
            float4* base = ob + (size_t)start * V4;
            const float4 zero = make_float4(0.f, 0.f, 0.f, 0.f);
            for (int i = tid; i < nf4; i += NT) base[i] = zero;   // coalesced
        }
    }
}

extern "C" void kernel_launch(void* const* d_in, const int* in_sizes, int n_in,
                              void* d_out, int out_size) {
    const float* xs = (const float*)d_in[0];
    const int* ds = (const int*)d_in[1];
    const int* ilens = (const int*)d_in[2];
    float* out = (float*)d_out;

    dim3 grid(SRC_BLOCKS + ZBLOCKS, BB);   // (120, 16) = 1920 blocks
    lr_kernel<<<grid, NT>>>(xs, ds, ilens, out);
}

// round 11
// speedup vs baseline: 1.0735x; 1.0735x over previous
#include <cuda_runtime.h>
#include <cstdint>

#define BB 16
#define TT 512
#define DD 384
#define OUT_LEN 3584            // T * (MAX_DUR - 1)
#define ROWS 8                  // output rows per block
#define BLOCKS_PER_B (OUT_LEN / ROWS)   // 448
#define NT 128
#define V4 (DD / 4)             // 96 float4 per row

// R8 geometry + forced 16 CTAs/SM (<=32 regs) + 2x3 batched gather to keep
// register pressure under the cap without spilling float4 data.
__global__ void __launch_bounds__(NT, 16)
lr_fused(const float* __restrict__ xs, const int* __restrict__ ds,
         const int* __restrict__ ilens, float* __restrict__ out) {
    __shared__ int csum[TT];
    __shared__ int wtot[4];
    __shared__ int srcs[ROWS];

    const int tid = threadIdx.x;
    const int lane = tid & 31;
    const int w = tid >> 5;
    const int b = blockIdx.y;
    const int r0 = blockIdx.x * ROWS;

    // ---- masked duration load: 4 consecutive per thread ----
    const int ilen = __ldg(ilens + b);
    int4 dv = ((const int4*)(ds + b * TT))[tid];
    const int g0 = tid * 4;
    int d0 = (g0 + 0 < ilen) ? dv.x : 0;
    int d1 = (g0 + 1 < ilen) ? dv.y : 0;
    int d2 = (g0 + 2 < ilen) ? dv.z : 0;
    int d3 = (g0 + 3 < ilen) ? dv.w : 0;
    int p1 = d0 + d1, p2 = p1 + d2, p3 = p2 + d3;

    // ---- block inclusive scan -> csum ----
    int x = p3;
    #pragma unroll
    for (int off = 1; off < 32; off <<= 1) {
        int y = __shfl_up_sync(0xFFFFFFFFu, x, off);
        if (lane >= off) x += y;
    }
    if (lane == 31) wtot[w] = x;
    __syncthreads();
    int woff = 0;
    #pragma unroll
    for (int i = 0; i < 4; ++i) woff += (i < w) ? wtot[i] : 0;
    const int excl = woff + x - p3;
    csum[g0 + 0] = excl + d0;
    csum[g0 + 1] = excl + p1;
    csum[g0 + 2] = excl + p2;
    csum[g0 + 3] = excl + p3;
    __syncthreads();

    const int total = csum[TT - 1];
    const int p = min(max(total - r0, 0), ROWS);   // valid rows are a prefix

    // ---- searchsorted(csum, t, 'right'): 10 halvings for [0,512] ----
    if (tid < ROWS) {
        int s = -1;
        if (tid < p) {
            const int t = r0 + tid;
            int lo = 0, hi = TT;
            #pragma unroll
            for (int it = 0; it < 10; ++it) {
                int mid = (lo + hi) >> 1;
                if (csum[mid] <= t) lo = mid + 1; else hi = mid;
            }
            s = lo;
        }
        srcs[tid] = s;
    }
    __syncthreads();

    // ---- gather: 768 float4 over 128 threads, 2 batches of 3 (MLP=3) ----
    const float4* __restrict__ xb = (const float4*)xs + (size_t)b * TT * V4;
    float4* __restrict__ ob = (float4*)out + ((size_t)b * OUT_LEN + r0) * V4;

    #pragma unroll
    for (int h = 0; h < 2; ++h) {
        float4 v[3];
        int fo[3];
        #pragma unroll
        for (int i = 0; i < 3; ++i) {
            const int f = tid + (h * 3 + i) * NT;
            const int rl = f / V4;                 // mul-shift (const div)
            const int c = f - rl * V4;
            const int s = srcs[rl];
            fo[i] = f;
            v[i] = make_float4(0.f, 0.f, 0.f, 0.f);
            if (s >= 0) v[i] = xb[s * V4 + c];     // coalesced LDG.128
        }
        #pragma unroll
        for (int i = 0; i < 3; ++i)
            ob[fo[i]] = v[i];                      // coalesced STG.128
    }
}

extern "C" void kernel_launch(void* const* d_in, const int* in_sizes, int n_in,
                              void* d_out, int out_size) {
    const float* xs = (const float*)d_in[0];
    const int* ds = (const int*)d_in[1];
    const int* ilens = (const int*)d_in[2];
    float* out = (float*)d_out;

    dim3 grid(BLOCKS_PER_B, BB);    // (448, 16) = 7168 blocks
    lr_fused<<<grid, NT>>>(xs, ds, ilens, out);
}